// round 16
// baseline (speedup 1.0000x reference)
#include <cuda_runtime.h>
#include <cstdint>

#define HD   19      // hidden size
#define HJ   20      // padded row stride
#define DD   64      // input size
#define TPB  128
#define RPT  2       // batch rows per thread in k_main
#define RPB  (TPB * RPT)
#define BMAX 524288
#define NPART 4096   // k_b_map grid

__device__ float g_partials[NPART];
__device__ float g_mapped[(size_t)HD * BMAX];   // mapped, [j][row] column-major

struct Tables {
    float WiT[DD * HJ];   // [k][j] = Wi[j][k]
    float bi[HJ];
    float WrT[HD * HJ];   // [k][j] = Wr[j][k]
    float WoT[HD * HJ];   // [k][j] = Wo[j][k]
    float bo[HJ];
    float bdt[HJ];        // dt / tau_dyn
};
__device__ Tables g_tab;            // staging
__constant__ Tables c_tab;          // uniform-path weights
#define WI_BYTES ((DD * HJ + HJ) * 4)           // WiT + bi region
#define TAB_F ((int)(sizeof(Tables) / 4))

static __device__ __forceinline__ float tanha(float v) {
    float r; asm("tanh.approx.f32 %0,%1;" : "=f"(r) : "f"(v)); return r;
}

// ---------- kernel 0: transpose Wi + bi into staging ----------
__global__ void __launch_bounds__(256) k_tr(
    const float* __restrict__ Wi, const float* __restrict__ bi)
{
    int t = threadIdx.x;
    for (int i = t; i < DD * HJ + HJ; i += 256) ((float*)&g_tab)[i] = 0.f;
    __syncthreads();
    for (int i = t; i < DD * HD; i += 256) {
        int k = i / HD, j = i % HD;
        g_tab.WiT[k * HJ + j] = Wi[j * DD + k];
    }
    if (t < HD) g_tab.bi[t] = bi[t];
}

// ---------- kernel 1: |x| partials + mapped = x @ Wi^T + bi ----------
__global__ void __launch_bounds__(TPB) k_b_map(
    const float* __restrict__ x, int B)
{
    __shared__ __align__(16) float sx[TPB * 68];   // x tile, row stride 17 float4
    __shared__ float red[TPB / 32];
    const int tid = threadIdx.x;

    // coalesced x tile load (128 rows x 64 floats)
    const float4* xg = (const float4*)(x + (size_t)blockIdx.x * (TPB * DD));
    float4* sx4 = (float4*)sx;
    for (int i = tid; i < TPB * (DD / 4); i += TPB) {
        int row = i >> 4, q = i & 15;
        sx4[row * 17 + q] = xg[i];
    }
    __syncthreads();

    // own row -> registers
    float xv[DD];
    {
        const float4* rp = sx4 + tid * 17;
#pragma unroll
        for (int q = 0; q < 16; q++) {
            float4 v = rp[q];
            xv[4 * q] = v.x; xv[4 * q + 1] = v.y;
            xv[4 * q + 2] = v.z; xv[4 * q + 3] = v.w;
        }
    }

    // |x| partial
    float s = 0.f;
#pragma unroll
    for (int k = 0; k < DD; k++) s += fabsf(xv[k]);
#pragma unroll
    for (int o = 16; o > 0; o >>= 1) s += __shfl_down_sync(0xffffffffu, s, o);
    if ((tid & 31) == 0) red[tid >> 5] = s;

    // mapped (constant-path weights, same accumulation order as before)
    float m[HD];
#pragma unroll
    for (int j = 0; j < HD; j++) m[j] = c_tab.bi[j];
#pragma unroll 4
    for (int k = 0; k < DD; k++) {
        float xk = xv[k];
#pragma unroll
        for (int j = 0; j < HD; j++)
            m[j] = fmaf(xk, c_tab.WiT[k * HJ + j], m[j]);
    }
    const size_t row = (size_t)blockIdx.x * TPB + tid;
#pragma unroll
    for (int j = 0; j < HD; j++)
        g_mapped[(size_t)j * B + row] = m[j];

    __syncthreads();
    if (tid == 0) {
        float t = 0.f;
#pragma unroll
        for (int i = 0; i < TPB / 32; i++) t += red[i];
        g_partials[blockIdx.x] = t;
    }
}

// ---------- kernel 2: finish reduction + build Wr/Wo/bdt tables ----------
__global__ void __launch_bounds__(256) k_prep(
    const float* __restrict__ Wr, const float* __restrict__ Wo,
    const float* __restrict__ bo, const float* __restrict__ tau,
    const float* __restrict__ ta, float invN)
{
    __shared__ float red[256];
    __shared__ float urg_s;
    int t = threadIdx.x;

    float s = 0.f;
    for (int i = t; i < NPART; i += 256) s += g_partials[i];
    red[t] = s;
    __syncthreads();
#pragma unroll
    for (int o = 128; o > 0; o >>= 1) {
        if (t < o) red[t] += red[t + o];
        __syncthreads();
    }
    if (t == 0) urg_s = fmaxf(red[0] * invN, 0.01f);

    // zero only the regions this kernel owns (WrT..end)
    {
        float* base = (float*)&g_tab.WrT[0];
        const int n = TAB_F - (DD * HJ + HJ);
        for (int i = t; i < n; i += 256) base[i] = 0.f;
    }
    __syncthreads();
    float urg = urg_s;

    for (int i = t; i < HD * HD; i += 256) {
        int k = i / HD, j = i % HD;
        g_tab.WrT[k * HJ + j] = Wr[j * HD + k];
        g_tab.WoT[k * HJ + j] = Wo[j * HD + k];
    }
    if (t < HD) {
        g_tab.bo[t] = bo[t];
        float td = tau[t] * (1.0f - ta[t]) + ta[t] / urg;
        td = fminf(fmaxf(td, 0.01f), 10.0f);
        g_tab.bdt[t] = 0.01f / td;
    }
}

// ---------- kernel 3: recurrence + output, constant weights, RPT=2 ----------
__global__ void __launch_bounds__(TPB)
k_main(const int* __restrict__ steps_p, float* __restrict__ out,
       float* __restrict__ hout, int B)
{
    __shared__ float mst[RPB * HD];     // mapped staging [j][r][tid]; then output

    const int tid = threadIdx.x;
    const size_t row0 = (size_t)blockIdx.x * RPB + tid;

    // ---- phase 1': load mapped (coalesced) into smem ----
#pragma unroll
    for (int j = 0; j < HD; j++) {
        mst[(j * RPT + 0) * TPB + tid] = g_mapped[(size_t)j * B + row0];
        mst[(j * RPT + 1) * TPB + tid] = g_mapped[(size_t)j * B + row0 + TPB];
    }
    // threads only read their own slots below; no block sync needed

    // ---- phase 2: recurrence ----
    float h0[HD], h1[HD];
#pragma unroll
    for (int j = 0; j < HD; j++) { h0[j] = 0.f; h1[j] = 0.f; }

    const int steps = *steps_p;
    for (int s = 0; s < steps; s++) {
        float a0[HD], a1[HD];
#pragma unroll
        for (int j = 0; j < HD; j++) {
            a0[j] = mst[(j * RPT + 0) * TPB + tid];
            a1[j] = mst[(j * RPT + 1) * TPB + tid];
        }
#pragma unroll
        for (int k = 0; k < HD; k++) {
            float hk0 = h0[k], hk1 = h1[k];
#pragma unroll
            for (int j = 0; j < HD; j++) {
                float w = c_tab.WrT[k * HJ + j];
                a0[j] = fmaf(hk0, w, a0[j]);
                a1[j] = fmaf(hk1, w, a1[j]);
            }
        }
#pragma unroll
        for (int j = 0; j < HD; j++) {
            float b = c_tab.bdt[j];
            h0[j] = fmaf(b, tanha(a0[j]) - h0[j], h0[j]);
            h1[j] = fmaf(b, tanha(a1[j]) - h1[j], h1[j]);
        }
    }

    // ---- phase 3: out = h @ Wo^T + bo ----
    float o0[HD], o1[HD];
#pragma unroll
    for (int j = 0; j < HD; j++) { o0[j] = c_tab.bo[j]; o1[j] = c_tab.bo[j]; }
#pragma unroll
    for (int k = 0; k < HD; k++) {
        float hk0 = h0[k], hk1 = h1[k];
#pragma unroll
        for (int j = 0; j < HD; j++) {
            float w = c_tab.WoT[k * HJ + j];
            o0[j] = fmaf(hk0, w, o0[j]);
            o1[j] = fmaf(hk1, w, o1[j]);
        }
    }

    // ---- stage + coalesced stores (reuse mst) ----
    __syncthreads();
#pragma unroll
    for (int j = 0; j < HD; j++) {
        mst[tid * HD + j]         = o0[j];
        mst[(TPB + tid) * HD + j] = o1[j];
    }
    __syncthreads();
    {
        float4* go = (float4*)(out + (size_t)blockIdx.x * (RPB * HD));
        const float4* f4 = (const float4*)mst;
        for (int i = tid; i < RPB * HD / 4; i += TPB) go[i] = f4[i];
    }
    if (hout) {
        __syncthreads();
#pragma unroll
        for (int j = 0; j < HD; j++) {
            mst[tid * HD + j]         = h0[j];
            mst[(TPB + tid) * HD + j] = h1[j];
        }
        __syncthreads();
        float4* gh = (float4*)(hout + (size_t)blockIdx.x * (RPB * HD));
        const float4* f4 = (const float4*)mst;
        for (int i = tid; i < RPB * HD / 4; i += TPB) gh[i] = f4[i];
    }
}

extern "C" void kernel_launch(void* const* d_in, const int* in_sizes, int n_in,
                              void* d_out, int out_size) {
    const float* x   = (const float*)d_in[0];
    const float* Wi  = (const float*)d_in[1];
    const float* bi  = (const float*)d_in[2];
    const float* Wr  = (const float*)d_in[3];
    const float* Wo  = (const float*)d_in[4];
    const float* bo  = (const float*)d_in[5];
    const float* tau = (const float*)d_in[6];
    const float* ta  = (const float*)d_in[7];
    const int* steps = (const int*)d_in[8];

    const int nx = in_sizes[0];
    const int B  = nx / DD;

    float* out = (float*)d_out;
    long long bh = (long long)B * HD;
    float* hout = ((long long)out_size >= 2 * bh) ? (out + bh) : nullptr;

    static void* g_tab_addr = nullptr;
    if (!g_tab_addr) cudaGetSymbolAddress(&g_tab_addr, g_tab);

    k_tr<<<1, 256>>>(Wi, bi);
    cudaMemcpyToSymbolAsync(c_tab, g_tab_addr, WI_BYTES, 0,
                            cudaMemcpyDeviceToDevice, 0);
    k_b_map<<<B / TPB, TPB>>>(x, B);
    k_prep<<<1, 256>>>(Wr, Wo, bo, tau, ta, 1.0f / (float)nx);
    cudaMemcpyToSymbolAsync(c_tab, g_tab_addr, sizeof(Tables), 0,
                            cudaMemcpyDeviceToDevice, 0);
    k_main<<<B / RPB, TPB>>>(steps, out, hout, B);
}

// round 17
// speedup vs baseline: 1.2347x; 1.2347x over previous
#include <cuda_runtime.h>
#include <cstdint>

#define HD   19      // hidden size
#define HJ   20      // padded row stride
#define DD   64      // input size
#define TPB  128
#define RPT  2       // batch rows per thread in k_main
#define RPB  (TPB * RPT)
#define BMAX 524288
#define NPART 4096   // k_b_map grid

__device__ float g_partials[NPART];
__device__ float g_mapped[(size_t)HD * BMAX];   // mapped, [j][row] column-major

struct Tables {
    float WiT[DD * HJ];   // [k][j] = Wi[j][k]
    float bi[HJ];
    float WrT[HD * HJ];   // [k][j] = Wr[j][k]
    float WoT[HD * HJ];   // [k][j] = Wo[j][k]
    float bo[HJ];
    float bdt[HJ];        // dt / tau_dyn
};
__device__ Tables g_tab;            // staging
__constant__ Tables c_tab;          // uniform-path weights
#define WI_BYTES ((DD * HJ + HJ) * 4)           // WiT + bi region
#define TAB_F ((int)(sizeof(Tables) / 4))

static __device__ __forceinline__ float tanha(float v) {
    float r; asm("tanh.approx.f32 %0,%1;" : "=f"(r) : "f"(v)); return r;
}

// ---------- kernel 0: transpose Wi + bi into staging ----------
__global__ void __launch_bounds__(256) k_tr(
    const float* __restrict__ Wi, const float* __restrict__ bi)
{
    int t = threadIdx.x;
    for (int i = t; i < DD * HJ + HJ; i += 256) ((float*)&g_tab)[i] = 0.f;
    __syncthreads();
    for (int i = t; i < DD * HD; i += 256) {
        int k = i / HD, j = i % HD;
        g_tab.WiT[k * HJ + j] = Wi[j * DD + k];
    }
    if (t < HD) g_tab.bi[t] = bi[t];
}

// ---------- kernel 1: |x| partials + mapped = x @ Wi^T + bi ----------
// Direct float4 row loads, constant-path weights, no smem staging.
__global__ void __launch_bounds__(TPB) k_b_map(
    const float* __restrict__ x, int B)
{
    __shared__ float red[TPB / 32];
    const int tid = threadIdx.x;
    const size_t row = (size_t)blockIdx.x * TPB + tid;
    const float4* xr = (const float4*)(x + row * DD);

    float m[HD];
#pragma unroll
    for (int j = 0; j < HD; j++) m[j] = c_tab.bi[j];

    float s = 0.f;
#pragma unroll 4
    for (int q = 0; q < DD / 4; q++) {
        float4 v = xr[q];
        s += fabsf(v.x) + fabsf(v.y) + fabsf(v.z) + fabsf(v.w);
        float vv[4] = {v.x, v.y, v.z, v.w};
#pragma unroll
        for (int e = 0; e < 4; e++) {
            const int k = q * 4 + e;
            float xk = vv[e];
#pragma unroll
            for (int j = 0; j < HD; j++)
                m[j] = fmaf(xk, c_tab.WiT[k * HJ + j], m[j]);
        }
    }

    // coalesced column-major mapped stores
#pragma unroll
    for (int j = 0; j < HD; j++)
        g_mapped[(size_t)j * B + row] = m[j];

    // |x| block partial
#pragma unroll
    for (int o = 16; o > 0; o >>= 1) s += __shfl_down_sync(0xffffffffu, s, o);
    if ((tid & 31) == 0) red[tid >> 5] = s;
    __syncthreads();
    if (tid == 0) {
        float t = 0.f;
#pragma unroll
        for (int i = 0; i < TPB / 32; i++) t += red[i];
        g_partials[blockIdx.x] = t;
    }
}

// ---------- kernel 2: finish reduction + build Wr/Wo/bdt tables ----------
__global__ void __launch_bounds__(256) k_prep(
    const float* __restrict__ Wr, const float* __restrict__ Wo,
    const float* __restrict__ bo, const float* __restrict__ tau,
    const float* __restrict__ ta, float invN)
{
    __shared__ float red[256];
    __shared__ float urg_s;
    int t = threadIdx.x;

    float s = 0.f;
    for (int i = t; i < NPART; i += 256) s += g_partials[i];
    red[t] = s;
    __syncthreads();
#pragma unroll
    for (int o = 128; o > 0; o >>= 1) {
        if (t < o) red[t] += red[t + o];
        __syncthreads();
    }
    if (t == 0) urg_s = fmaxf(red[0] * invN, 0.01f);

    // zero only the regions this kernel owns (WrT..end)
    {
        float* base = (float*)&g_tab.WrT[0];
        const int n = TAB_F - (DD * HJ + HJ);
        for (int i = t; i < n; i += 256) base[i] = 0.f;
    }
    __syncthreads();
    float urg = urg_s;

    for (int i = t; i < HD * HD; i += 256) {
        int k = i / HD, j = i % HD;
        g_tab.WrT[k * HJ + j] = Wr[j * HD + k];
        g_tab.WoT[k * HJ + j] = Wo[j * HD + k];
    }
    if (t < HD) {
        g_tab.bo[t] = bo[t];
        float td = tau[t] * (1.0f - ta[t]) + ta[t] / urg;
        td = fminf(fmaxf(td, 0.01f), 10.0f);
        g_tab.bdt[t] = 0.01f / td;
    }
}

// ---------- kernel 3: recurrence + output, constant weights, RPT=2 ----------
// (unchanged from R16 — measured 92 us, issue=82%)
__global__ void __launch_bounds__(TPB)
k_main(const int* __restrict__ steps_p, float* __restrict__ out,
       float* __restrict__ hout, int B)
{
    __shared__ float mst[RPB * HD];     // mapped staging [j][r][tid]; then output

    const int tid = threadIdx.x;
    const size_t row0 = (size_t)blockIdx.x * RPB + tid;

    // ---- phase 1': load mapped (coalesced) into smem ----
#pragma unroll
    for (int j = 0; j < HD; j++) {
        mst[(j * RPT + 0) * TPB + tid] = g_mapped[(size_t)j * B + row0];
        mst[(j * RPT + 1) * TPB + tid] = g_mapped[(size_t)j * B + row0 + TPB];
    }
    // threads only read their own slots below; no block sync needed

    // ---- phase 2: recurrence ----
    float h0[HD], h1[HD];
#pragma unroll
    for (int j = 0; j < HD; j++) { h0[j] = 0.f; h1[j] = 0.f; }

    const int steps = *steps_p;
    for (int s = 0; s < steps; s++) {
        float a0[HD], a1[HD];
#pragma unroll
        for (int j = 0; j < HD; j++) {
            a0[j] = mst[(j * RPT + 0) * TPB + tid];
            a1[j] = mst[(j * RPT + 1) * TPB + tid];
        }
#pragma unroll
        for (int k = 0; k < HD; k++) {
            float hk0 = h0[k], hk1 = h1[k];
#pragma unroll
            for (int j = 0; j < HD; j++) {
                float w = c_tab.WrT[k * HJ + j];
                a0[j] = fmaf(hk0, w, a0[j]);
                a1[j] = fmaf(hk1, w, a1[j]);
            }
        }
#pragma unroll
        for (int j = 0; j < HD; j++) {
            float b = c_tab.bdt[j];
            h0[j] = fmaf(b, tanha(a0[j]) - h0[j], h0[j]);
            h1[j] = fmaf(b, tanha(a1[j]) - h1[j], h1[j]);
        }
    }

    // ---- phase 3: out = h @ Wo^T + bo ----
    float o0[HD], o1[HD];
#pragma unroll
    for (int j = 0; j < HD; j++) { o0[j] = c_tab.bo[j]; o1[j] = c_tab.bo[j]; }
#pragma unroll
    for (int k = 0; k < HD; k++) {
        float hk0 = h0[k], hk1 = h1[k];
#pragma unroll
        for (int j = 0; j < HD; j++) {
            float w = c_tab.WoT[k * HJ + j];
            o0[j] = fmaf(hk0, w, o0[j]);
            o1[j] = fmaf(hk1, w, o1[j]);
        }
    }

    // ---- stage + coalesced stores (reuse mst) ----
    __syncthreads();
#pragma unroll
    for (int j = 0; j < HD; j++) {
        mst[tid * HD + j]         = o0[j];
        mst[(TPB + tid) * HD + j] = o1[j];
    }
    __syncthreads();
    {
        float4* go = (float4*)(out + (size_t)blockIdx.x * (RPB * HD));
        const float4* f4 = (const float4*)mst;
        for (int i = tid; i < RPB * HD / 4; i += TPB) go[i] = f4[i];
    }
    if (hout) {
        __syncthreads();
#pragma unroll
        for (int j = 0; j < HD; j++) {
            mst[tid * HD + j]         = h0[j];
            mst[(TPB + tid) * HD + j] = h1[j];
        }
        __syncthreads();
        float4* gh = (float4*)(hout + (size_t)blockIdx.x * (RPB * HD));
        const float4* f4 = (const float4*)mst;
        for (int i = tid; i < RPB * HD / 4; i += TPB) gh[i] = f4[i];
    }
}

extern "C" void kernel_launch(void* const* d_in, const int* in_sizes, int n_in,
                              void* d_out, int out_size) {
    const float* x   = (const float*)d_in[0];
    const float* Wi  = (const float*)d_in[1];
    const float* bi  = (const float*)d_in[2];
    const float* Wr  = (const float*)d_in[3];
    const float* Wo  = (const float*)d_in[4];
    const float* bo  = (const float*)d_in[5];
    const float* tau = (const float*)d_in[6];
    const float* ta  = (const float*)d_in[7];
    const int* steps = (const int*)d_in[8];

    const int nx = in_sizes[0];
    const int B  = nx / DD;

    float* out = (float*)d_out;
    long long bh = (long long)B * HD;
    float* hout = ((long long)out_size >= 2 * bh) ? (out + bh) : nullptr;

    static void* g_tab_addr = nullptr;
    if (!g_tab_addr) cudaGetSymbolAddress(&g_tab_addr, g_tab);

    k_tr<<<1, 256>>>(Wi, bi);
    cudaMemcpyToSymbolAsync(c_tab, g_tab_addr, WI_BYTES, 0,
                            cudaMemcpyDeviceToDevice, 0);
    k_b_map<<<B / TPB, TPB>>>(x, B);
    k_prep<<<1, 256>>>(Wr, Wo, bo, tau, ta, 1.0f / (float)nx);
    cudaMemcpyToSymbolAsync(c_tab, g_tab_addr, sizeof(Tables), 0,
                            cudaMemcpyDeviceToDevice, 0);
    k_main<<<B / RPB, TPB>>>(steps, out, hout, B);
}